// round 12
// baseline (speedup 1.0000x reference)
#include <cuda_runtime.h>
#include <math.h>

#define BB 2048
#define TT 16
#define RR 2048
#define TPB 128
#define NPAIR 15
#define NW (TPB / 32)
#define NCTA (BB * 2)   // two half-row CTAs per b

// 32 accumulator slots: [0..14] step sums, [15..29] step counts,
// [30] bce*vm sum, [31] vm sum. Zero at module load; the elected last
// block re-zeroes after reading, so graph replays always start clean.
__device__ float        g_acc[32];
__device__ unsigned int g_done;   // completion counter, reset by last block

__device__ __forceinline__ float log_sigmoid(float x) {
    return fminf(x, 0.f) - log1pf(__expf(-fabsf(x)));
}

__device__ __forceinline__ float pen1(float a, float b) {
    float d = fabsf(a - b);
    float e = fmaxf(d - 0.2f, 0.f);
    return e * e;
}

__global__ __launch_bounds__(TPB)
void fused_loss_kernel(const float* __restrict__ pred,
                       const float* __restrict__ rs,
                       const int*   __restrict__ tgt,
                       const int*   __restrict__ vmask,
                       float*       __restrict__ out)
{
    const int b    = blockIdx.x >> 1;
    const int half = blockIdx.x & 1;
    const int tid  = threadIdx.x;
    const int lane = tid & 31;
    const int wid  = tid >> 5;

    __shared__ float s_part[NPAIR * TPB];   // per-thread per-pair partials
    __shared__ float s_vm[TT];
    __shared__ float s_bce[TT];
    __shared__ float red[NPAIR];
    __shared__ bool  s_last;

    // ---- tiny BCE/vm part: threads 0..15 handle the 16 timesteps ----
    if (tid < TT) {
        int idx   = b * TT + tid;
        float v   = (float)vmask[idx];
        float y   = (float)tgt[idx];
        float p   = pred[idx];
        float bce = -(2.f * y * log_sigmoid(p) + (1.f - y) * log_sigmoid(-p));
        s_vm[tid]  = v;
        s_bce[tid] = bce * v;
    }

    // ---- streaming smoothness: this CTA covers half a r-row (1024 floats);
    //      each thread owns 8 r columns as 2 independent float4 chains
    //      (the per-thread shape that measured best). Plain full unroll.
    const float4* base = (const float4*)rs
                       + (size_t)b * TT * (RR / 4) + half * (RR / 8);
    float4 p0 = __ldcs(&base[tid]);
    float4 p1 = __ldcs(&base[tid + TPB]);

#pragma unroll
    for (int t = 1; t < TT; t++) {
        float4 c0 = __ldcs(&base[t * (RR / 4) + tid]);
        float4 c1 = __ldcs(&base[t * (RR / 4) + tid + TPB]);
        float a = 0.f;
        a += pen1(c0.x, p0.x);  a += pen1(c0.y, p0.y);
        a += pen1(c0.z, p0.z);  a += pen1(c0.w, p0.w);
        a += pen1(c1.x, p1.x);  a += pen1(c1.y, p1.y);
        a += pen1(c1.z, p1.z);  a += pen1(c1.w, p1.w);
        s_part[(t - 1) * TPB + tid] = a;
        p0 = c0; p1 = c1;
    }
    __syncthreads();

    // ---- cooperative reduction: warp w folds pairs t = w, w+4, w+8, w+12 ----
    for (int t = wid; t < NPAIR; t += NW) {
        float s = 0.f;
#pragma unroll
        for (int k = 0; k < TPB / 32; k++)
            s += s_part[t * TPB + lane * (TPB / 32) + k];
#pragma unroll
        for (int o = 16; o; o >>= 1) s += __shfl_xor_sync(0xffffffffu, s, o);
        if (lane == 0) red[t] = s;
    }
    __syncthreads();

    // ---- global accumulation (REDG). Sums: both halves; counts/BCE: half 0 ----
    if (tid < NPAIR) {
        float pv = (s_vm[tid] > 0.5f && s_vm[tid + 1] > 0.5f) ? 1.f : 0.f;
        if (pv > 0.f) {
            atomicAdd(&g_acc[tid], red[tid]);
            if (half == 0) atomicAdd(&g_acc[NPAIR + tid], 1.f);
        }
    }
    if (tid == 0 && half == 0) {
        float bs = 0.f, vs = 0.f;
#pragma unroll
        for (int t = 0; t < TT; t++) { bs += s_bce[t]; vs += s_vm[t]; }
        atomicAdd(&g_acc[30], bs);
        atomicAdd(&g_acc[31], vs);
    }
    __syncthreads();

    // ---- last-block-done election ----
    if (tid == 0) {
        __threadfence();  // make this block's atomics visible before signaling
        unsigned prev = atomicAdd(&g_done, 1u);
        s_last = (prev == (unsigned)(NCTA - 1));
    }
    __syncthreads();

    if (s_last && tid < 32) {
        float v = g_acc[tid];
        // reset for the next graph replay (value already consumed)
        g_acc[tid] = 0.f;
        if (tid == 0) g_done = 0u;

        float ssum = 0.f;
        int ns = 0;
#pragma unroll
        for (int t = 0; t < NPAIR; t++) {
            float s = __shfl_sync(0xffffffffu, v, t);
            float c = __shfl_sync(0xffffffffu, v, NPAIR + t);
            if (c > 0.f) ns++;
            ssum += s / ((float)RR * fmaxf(c, 1.f));
        }
        float bs = __shfl_sync(0xffffffffu, v, 30);
        float vs = __shfl_sync(0xffffffffu, v, 31);
        if (tid == 0) {
            float smooth = (ns > 0) ? (ssum / (float)ns) : 0.f;
            float cls    = bs / fmaxf(vs, 1e-8f);
            out[0] = cls + 0.2f * smooth;
        }
    }
}

extern "C" void kernel_launch(void* const* d_in, const int* in_sizes, int n_in,
                              void* d_out, int out_size)
{
    const float* pred  = (const float*)d_in[0];  // [B,T,1]
    const float* rs    = (const float*)d_in[1];  // [B,T,R,1]
    const int*   tgt   = (const int*)d_in[2];    // [B,T]
    const int*   vmask = (const int*)d_in[3];    // [B,T]
    float*       out   = (float*)d_out;

    fused_loss_kernel<<<NCTA, TPB>>>(pred, rs, tgt, vmask, out);
}

// round 13
// speedup vs baseline: 1.0218x; 1.0218x over previous
#include <cuda_runtime.h>
#include <math.h>

#define BB 2048
#define TT 16
#define RR 2048
#define TPB 256
#define NPAIR 15

// 32 accumulator slots: [0..14] step sums, [15..29] step counts,
// [30] bce*vm sum, [31] vm sum. Zero at module load; the elected last
// block re-zeroes after reading, so graph replays always start clean.
__device__ float        g_acc[32];
__device__ unsigned int g_done;   // completion counter, reset by last block

__device__ __forceinline__ float log_sigmoid(float x) {
    return fminf(x, 0.f) - log1pf(__expf(-fabsf(x)));
}

__device__ __forceinline__ float pen1(float a, float b) {
    float d = fabsf(a - b);
    float e = fmaxf(d - 0.2f, 0.f);
    return e * e;
}

__global__ __launch_bounds__(TPB)
void fused_loss_kernel(const float* __restrict__ pred,
                       const float* __restrict__ rs,
                       const int*   __restrict__ tgt,
                       const int*   __restrict__ vmask,
                       float*       __restrict__ out)
{
    const int b    = blockIdx.x;
    const int tid  = threadIdx.x;
    const int lane = tid & 31;
    const int wid  = tid >> 5;

    __shared__ float s_part[NPAIR * TPB];   // per-thread per-pair partials
    __shared__ float s_vm[TT];
    __shared__ float s_bce[TT];
    __shared__ float red[NPAIR];
    __shared__ bool  s_last;

    // ---- streaming smoothness: each thread owns 8 r columns (2 float4) ----
    // Identical mainloop to the measured-best kernel (R9): plain full unroll,
    // per-t partial straight to shared, no in-loop shfl, no manual prefetch.
    const float4* base = (const float4*)rs + (size_t)b * TT * (RR / 4);
    float4 p0 = __ldcs(&base[tid]);
    float4 p1 = __ldcs(&base[tid + TPB]);

#pragma unroll
    for (int t = 1; t < TT; t++) {
        float4 c0 = __ldcs(&base[t * (RR / 4) + tid]);
        float4 c1 = __ldcs(&base[t * (RR / 4) + tid + TPB]);
        float a = 0.f;
        a += pen1(c0.x, p0.x);  a += pen1(c0.y, p0.y);
        a += pen1(c0.z, p0.z);  a += pen1(c0.w, p0.w);
        a += pen1(c1.x, p1.x);  a += pen1(c1.y, p1.y);
        a += pen1(c1.z, p1.z);  a += pen1(c1.w, p1.w);
        s_part[(t - 1) * TPB + tid] = a;
        p0 = c0; p1 = c1;
    }

    // ---- tiny BCE part AFTER the stream loop: its scalar loads overlap the
    //      loop tail instead of delaying the stream's first LDGs. Writes land
    //      before the same __syncthreads, so semantics are unchanged.
    if (tid < TT) {
        int idx   = b * TT + tid;
        float v   = (float)vmask[idx];
        float y   = (float)tgt[idx];
        float p   = pred[idx];
        float bce = -(2.f * y * log_sigmoid(p) + (1.f - y) * log_sigmoid(-p));
        s_vm[tid]  = v;
        s_bce[tid] = bce * v;
    }
    __syncthreads();

    // ---- cooperative reduction: warp w folds pairs t = w, w+8 ----
    for (int t = wid; t < NPAIR; t += TPB / 32) {
        float s = 0.f;
#pragma unroll
        for (int k = 0; k < TPB / 32; k++)
            s += s_part[t * TPB + lane * (TPB / 32) + k];
#pragma unroll
        for (int o = 16; o; o >>= 1) s += __shfl_xor_sync(0xffffffffu, s, o);
        if (lane == 0) red[t] = s;
    }
    __syncthreads();

    // ---- global accumulation via atomics (REDG; hidden under DRAM stream) ----
    if (tid < NPAIR) {
        float pv = (s_vm[tid] > 0.5f && s_vm[tid + 1] > 0.5f) ? 1.f : 0.f;
        if (pv > 0.f) {
            atomicAdd(&g_acc[tid], red[tid]);
            atomicAdd(&g_acc[NPAIR + tid], 1.f);
        }
    }
    if (tid == 0) {
        float bs = 0.f, vs = 0.f;
#pragma unroll
        for (int t = 0; t < TT; t++) { bs += s_bce[t]; vs += s_vm[t]; }
        atomicAdd(&g_acc[30], bs);
        atomicAdd(&g_acc[31], vs);
    }
    __syncthreads();

    // ---- last-block-done election ----
    if (tid == 0) {
        __threadfence();  // make this block's atomics visible before signaling
        unsigned prev = atomicAdd(&g_done, 1u);
        s_last = (prev == (unsigned)(BB - 1));
    }
    __syncthreads();

    if (s_last && tid < 32) {
        float v = g_acc[tid];
        // reset for the next graph replay (value already consumed)
        g_acc[tid] = 0.f;
        if (tid == 0) g_done = 0u;

        float ssum = 0.f;
        int ns = 0;
#pragma unroll
        for (int t = 0; t < NPAIR; t++) {
            float s = __shfl_sync(0xffffffffu, v, t);
            float c = __shfl_sync(0xffffffffu, v, NPAIR + t);
            if (c > 0.f) ns++;
            ssum += s / ((float)RR * fmaxf(c, 1.f));
        }
        float bs = __shfl_sync(0xffffffffu, v, 30);
        float vs = __shfl_sync(0xffffffffu, v, 31);
        if (tid == 0) {
            float smooth = (ns > 0) ? (ssum / (float)ns) : 0.f;
            float cls    = bs / fmaxf(vs, 1e-8f);
            out[0] = cls + 0.2f * smooth;
        }
    }
}

extern "C" void kernel_launch(void* const* d_in, const int* in_sizes, int n_in,
                              void* d_out, int out_size)
{
    const float* pred  = (const float*)d_in[0];  // [B,T,1]
    const float* rs    = (const float*)d_in[1];  // [B,T,R,1]
    const int*   tgt   = (const int*)d_in[2];    // [B,T]
    const int*   vmask = (const int*)d_in[3];    // [B,T]
    float*       out   = (float*)d_out;

    fused_loss_kernel<<<BB, TPB>>>(pred, rs, tgt, vmask, out);
}

// round 14
// speedup vs baseline: 1.0676x; 1.0448x over previous
#include <cuda_runtime.h>
#include <math.h>

#define BB 2048
#define TT 16
#define RR 2048
#define TPB 256
#define NPAIR 15

// 32 accumulator slots: [0..14] step sums, [15..29] step counts,
// [30] bce*vm sum, [31] vm sum. Zero at module load; the elected last
// block re-zeroes after reading, so graph replays always start clean.
__device__ float        g_acc[32];
__device__ unsigned int g_done;   // completion counter, reset by last block

__device__ __forceinline__ float log_sigmoid(float x) {
    return fminf(x, 0.f) - log1pf(__expf(-fabsf(x)));
}

__device__ __forceinline__ float pen1(float a, float b) {
    float d = fabsf(a - b);
    float e = fmaxf(d - 0.2f, 0.f);
    return e * e;
}

__global__ __launch_bounds__(TPB)
void fused_loss_kernel(const float* __restrict__ pred,
                       const float* __restrict__ rs,
                       const int*   __restrict__ tgt,
                       const int*   __restrict__ vmask,
                       float*       __restrict__ out)
{
    const int b    = blockIdx.x;
    const int tid  = threadIdx.x;
    const int lane = tid & 31;
    const int wid  = tid >> 5;

    __shared__ float s_part[NPAIR * TPB];   // per-thread per-pair partials
    __shared__ float s_vm[TT];
    __shared__ float s_bce[TT];
    __shared__ float red[NPAIR];
    __shared__ bool  s_last;

    // ---- tiny BCE part: threads 0..15 handle the 16 timesteps of this b ----
    if (tid < TT) {
        int idx   = b * TT + tid;
        float v   = (float)vmask[idx];
        float y   = (float)tgt[idx];
        float p   = pred[idx];
        float bce = -(2.f * y * log_sigmoid(p) + (1.f - y) * log_sigmoid(-p));
        s_vm[tid]  = v;
        s_bce[tid] = bce * v;
    }

    // ---- streaming smoothness: each thread owns 8 r columns (2 float4) ----
    // Per-t partial goes straight to shared (1 STS); no register accumulators,
    // no in-loop shfl -> minimal live state, max occupancy.
    const float4* base = (const float4*)rs + (size_t)b * TT * (RR / 4);
    float4 p0 = __ldcs(&base[tid]);
    float4 p1 = __ldcs(&base[tid + TPB]);

#pragma unroll
    for (int t = 1; t < TT; t++) {
        float4 c0 = __ldcs(&base[t * (RR / 4) + tid]);
        float4 c1 = __ldcs(&base[t * (RR / 4) + tid + TPB]);
        float a = 0.f;
        a += pen1(c0.x, p0.x);  a += pen1(c0.y, p0.y);
        a += pen1(c0.z, p0.z);  a += pen1(c0.w, p0.w);
        a += pen1(c1.x, p1.x);  a += pen1(c1.y, p1.y);
        a += pen1(c1.z, p1.z);  a += pen1(c1.w, p1.w);
        s_part[(t - 1) * TPB + tid] = a;
        p0 = c0; p1 = c1;
    }
    __syncthreads();

    // ---- cooperative reduction: warp w folds pairs t = w, w+8 ----
    for (int t = wid; t < NPAIR; t += TPB / 32) {
        float s = 0.f;
#pragma unroll
        for (int k = 0; k < TPB / 32; k++)
            s += s_part[t * TPB + lane * (TPB / 32) + k];
#pragma unroll
        for (int o = 16; o; o >>= 1) s += __shfl_xor_sync(0xffffffffu, s, o);
        if (lane == 0) red[t] = s;
    }
    __syncthreads();

    // ---- global accumulation via atomics (REDG; hidden under DRAM stream) ----
    if (tid < NPAIR) {
        float pv = (s_vm[tid] > 0.5f && s_vm[tid + 1] > 0.5f) ? 1.f : 0.f;
        if (pv > 0.f) {
            atomicAdd(&g_acc[tid], red[tid]);
            atomicAdd(&g_acc[NPAIR + tid], 1.f);
        }
    }
    if (tid == 0) {
        float bs = 0.f, vs = 0.f;
#pragma unroll
        for (int t = 0; t < TT; t++) { bs += s_bce[t]; vs += s_vm[t]; }
        atomicAdd(&g_acc[30], bs);
        atomicAdd(&g_acc[31], vs);
    }
    __syncthreads();

    // ---- last-block-done election ----
    if (tid == 0) {
        __threadfence();  // make this block's atomics visible before signaling
        unsigned prev = atomicAdd(&g_done, 1u);
        s_last = (prev == (unsigned)(BB - 1));
    }
    __syncthreads();

    if (s_last && tid < 32) {
        float v = g_acc[tid];
        // reset for the next graph replay (value already consumed)
        g_acc[tid] = 0.f;
        if (tid == 0) g_done = 0u;

        float ssum = 0.f;
        int ns = 0;
#pragma unroll
        for (int t = 0; t < NPAIR; t++) {
            float s = __shfl_sync(0xffffffffu, v, t);
            float c = __shfl_sync(0xffffffffu, v, NPAIR + t);
            if (c > 0.f) ns++;
            ssum += s / ((float)RR * fmaxf(c, 1.f));
        }
        float bs = __shfl_sync(0xffffffffu, v, 30);
        float vs = __shfl_sync(0xffffffffu, v, 31);
        if (tid == 0) {
            float smooth = (ns > 0) ? (ssum / (float)ns) : 0.f;
            float cls    = bs / fmaxf(vs, 1e-8f);
            out[0] = cls + 0.2f * smooth;
        }
    }
}

extern "C" void kernel_launch(void* const* d_in, const int* in_sizes, int n_in,
                              void* d_out, int out_size)
{
    const float* pred  = (const float*)d_in[0];  // [B,T,1]
    const float* rs    = (const float*)d_in[1];  // [B,T,R,1]
    const int*   tgt   = (const int*)d_in[2];    // [B,T]
    const int*   vmask = (const int*)d_in[3];    // [B,T]
    float*       out   = (float*)d_out;

    fused_loss_kernel<<<BB, TPB>>>(pred, rs, tgt, vmask, out);
}

// round 15
// speedup vs baseline: 1.7773x; 1.6648x over previous
#include <cuda_runtime.h>
#include <math.h>

#define BB 2048
#define TT 16
#define RR 2048
#define TPB 256
#define NPAIR 15

// 32 accumulator slots: [0..14] step sums, [15..29] step counts,
// [30] bce*vm sum, [31] vm sum. Zero at module load; the elected last
// block re-zeroes after reading, so graph replays always start clean.
__device__ float        g_acc[32];
__device__ unsigned int g_done;   // completion counter, reset by last block

__device__ __forceinline__ float log_sigmoid(float x) {
    return fminf(x, 0.f) - log1pf(__expf(-fabsf(x)));
}

__device__ __forceinline__ float pen1(float a, float b) {
    float d = fabsf(a - b);
    float e = fmaxf(d - 0.2f, 0.f);
    return e * e;
}

__global__ __launch_bounds__(TPB)
void fused_loss_kernel(const float* __restrict__ pred,
                       const float* __restrict__ rs,
                       const int*   __restrict__ tgt,
                       const int*   __restrict__ vmask,
                       float*       __restrict__ out)
{
    const int b    = blockIdx.x;
    const int tid  = threadIdx.x;
    const int lane = tid & 31;
    const int wid  = tid >> 5;

    __shared__ float s_part[NPAIR * TPB];   // per-thread per-pair partials
    __shared__ float s_vm[TT];
    __shared__ float s_bce[TT];
    __shared__ float red[NPAIR];
    __shared__ bool  s_last;

    // ---- tiny BCE part: threads 0..15 handle the 16 timesteps of this b ----
    if (tid < TT) {
        int idx   = b * TT + tid;
        float v   = (float)vmask[idx];
        float y   = (float)tgt[idx];
        float p   = pred[idx];
        float bce = -(2.f * y * log_sigmoid(p) + (1.f - y) * log_sigmoid(-p));
        s_vm[tid]  = v;
        s_bce[tid] = bce * v;
    }
    __syncthreads();   // all threads need s_vm to gate their loads

    // per-thread copy of validity bits (uniform across the block -> no divergence)
    bool vmt[TT];
#pragma unroll
    for (int t = 0; t < TT; t++) vmt[t] = (s_vm[t] > 0.5f);

    // ---- sparse streaming smoothness: only rows in >=1 valid pair are read.
    //      E[rows] ~= 5.75/16 -> ~36% of the 268MB ever touches DRAM.
    const float4* base = (const float4*)rs + (size_t)b * TT * (RR / 4);
    float4 p0, p1;

#pragma unroll
    for (int t = 0; t < TT; t++) {
        const bool pairv = (t > 0) && vmt[t - 1] && vmt[t];
        const bool needc = vmt[t] &&
                           ((t > 0 && vmt[t - 1]) || (t < TT - 1 && vmt[t + 1]));
        float4 c0, c1;
        if (needc) {
            c0 = __ldcs(&base[t * (RR / 4) + tid]);
            c1 = __ldcs(&base[t * (RR / 4) + tid + TPB]);
        }
        if (t > 0) {
            float a = 0.f;
            if (pairv) {   // p0/p1 were loaded: row t-1 was 'needc' when pairv
                a += pen1(c0.x, p0.x);  a += pen1(c0.y, p0.y);
                a += pen1(c0.z, p0.z);  a += pen1(c0.w, p0.w);
                a += pen1(c1.x, p1.x);  a += pen1(c1.y, p1.y);
                a += pen1(c1.z, p1.z);  a += pen1(c1.w, p1.w);
            }
            s_part[(t - 1) * TPB + tid] = a;
        }
        p0 = c0; p1 = c1;
    }
    __syncthreads();

    // ---- cooperative reduction: warp w folds pairs t = w, w+8 ----
    for (int t = wid; t < NPAIR; t += TPB / 32) {
        float s = 0.f;
#pragma unroll
        for (int k = 0; k < TPB / 32; k++)
            s += s_part[t * TPB + lane * (TPB / 32) + k];
#pragma unroll
        for (int o = 16; o; o >>= 1) s += __shfl_xor_sync(0xffffffffu, s, o);
        if (lane == 0) red[t] = s;
    }
    __syncthreads();

    // ---- global accumulation via atomics (REDG; hidden under DRAM stream) ----
    if (tid < NPAIR) {
        float pv = (s_vm[tid] > 0.5f && s_vm[tid + 1] > 0.5f) ? 1.f : 0.f;
        if (pv > 0.f) {
            atomicAdd(&g_acc[tid], red[tid]);
            atomicAdd(&g_acc[NPAIR + tid], 1.f);
        }
    }
    if (tid == 0) {
        float bs = 0.f, vs = 0.f;
#pragma unroll
        for (int t = 0; t < TT; t++) { bs += s_bce[t]; vs += s_vm[t]; }
        atomicAdd(&g_acc[30], bs);
        atomicAdd(&g_acc[31], vs);
    }
    __syncthreads();

    // ---- last-block-done election ----
    if (tid == 0) {
        __threadfence();  // make this block's atomics visible before signaling
        unsigned prev = atomicAdd(&g_done, 1u);
        s_last = (prev == (unsigned)(BB - 1));
    }
    __syncthreads();

    if (s_last && tid < 32) {
        float v = g_acc[tid];
        // reset for the next graph replay (value already consumed)
        g_acc[tid] = 0.f;
        if (tid == 0) g_done = 0u;

        float ssum = 0.f;
        int ns = 0;
#pragma unroll
        for (int t = 0; t < NPAIR; t++) {
            float s = __shfl_sync(0xffffffffu, v, t);
            float c = __shfl_sync(0xffffffffu, v, NPAIR + t);
            if (c > 0.f) ns++;
            ssum += s / ((float)RR * fmaxf(c, 1.f));
        }
        float bs = __shfl_sync(0xffffffffu, v, 30);
        float vs = __shfl_sync(0xffffffffu, v, 31);
        if (tid == 0) {
            float smooth = (ns > 0) ? (ssum / (float)ns) : 0.f;
            float cls    = bs / fmaxf(vs, 1e-8f);
            out[0] = cls + 0.2f * smooth;
        }
    }
}

extern "C" void kernel_launch(void* const* d_in, const int* in_sizes, int n_in,
                              void* d_out, int out_size)
{
    const float* pred  = (const float*)d_in[0];  // [B,T,1]
    const float* rs    = (const float*)d_in[1];  // [B,T,R,1]
    const int*   tgt   = (const int*)d_in[2];    // [B,T]
    const int*   vmask = (const int*)d_in[3];    // [B,T]
    float*       out   = (float*)d_out;

    fused_loss_kernel<<<BB, TPB>>>(pred, rs, tgt, vmask, out);
}